// round 16
// baseline (speedup 1.0000x reference)
#include <cuda_runtime.h>
#include <cuda_bf16.h>
#include <cstdint>
#include <math.h>

#define NN 50000
#define NE 800000
#define FD 50
#define FDP 64
#define HD 512
#define OD 121
#define NG 20
#define EPSV 1e-5f

// ---------------- scratch ---------------------------------------------------
__device__ float g_h1[(size_t)NN * HD];
__device__ int   g_degi[NN];
__device__ int   g_rowptr[NN + 1];
__device__ int   g_cursor[NN];
__device__ int   g_csr[NE];
__device__ float g_invsz[NG];
__device__ float g_gsum[NG * HD];
__device__ float g_gsq[NG * HD];
__device__ float g_gS[NG * HD];
__device__ float g_gT[NG * HD];
__device__ __nv_bfloat16 g_ah[(size_t)NN * HD];
__device__ __nv_bfloat16 g_al[(size_t)NN * HD];
__device__ __nv_bfloat16 g_xh[(size_t)NN * HD];
__device__ __nv_bfloat16 g_xl[(size_t)NN * HD];
#define WTOT 1762304
__device__ __nv_bfloat16 g_wh[WTOT];
__device__ __nv_bfloat16 g_wl[WTOT];

// ---------------- utility ---------------------------------------------------
__global__ void k_zero2f(float* __restrict__ a, float* __restrict__ b, int n) {
    int i = blockIdx.x * blockDim.x + threadIdx.x;
    if (i < n) { a[i] = 0.f; b[i] = 0.f; }
}

__global__ void k_zero2i(int* __restrict__ a, int* __restrict__ b, int n) {
    int i = blockIdx.x * blockDim.x + threadIdx.x;
    if (i < n) { a[i] = 0; b[i] = 0; }
}

__global__ void k_count_i(const int* __restrict__ idx, int* __restrict__ cnt, int n) {
    int i = blockIdx.x * blockDim.x + threadIdx.x;
    if (i < n) atomicAdd(&cnt[idx[i]], 1);
}

__global__ void k_group_sizes(const int* __restrict__ batch, float* __restrict__ invsz) {
    int g = threadIdx.x;
    if (g >= NG) return;
    int lo = 0, hi = NN;
    while (lo < hi) { int m = (lo + hi) >> 1; if (batch[m] < g) lo = m + 1; else hi = m; }
    int lb = lo;
    lo = 0; hi = NN;
    while (lo < hi) { int m = (lo + hi) >> 1; if (batch[m] < g + 1) lo = m + 1; else hi = m; }
    invsz[g] = 1.0f / fmaxf((float)(lo - lb), 1.0f);
}

__global__ void k_scan2(const int* __restrict__ deg, int* __restrict__ rowptr) {
    __shared__ int sh[1024];
    int tid = threadIdx.x;
    const int CH = (NN + 1023) / 1024;
    int start = tid * CH, end = min(start + CH, NN);
    int s = 0;
    for (int i = start; i < end; i++) s += deg[i];
    sh[tid] = s;
    __syncthreads();
    for (int d = 1; d < 1024; d <<= 1) {
        int v = (tid >= d) ? sh[tid - d] : 0;
        __syncthreads();
        sh[tid] += v;
        __syncthreads();
    }
    int off = sh[tid] - s;
    for (int i = start; i < end; i++) { rowptr[i] = off; off += deg[i]; }
    if (tid == 1023) rowptr[NN] = sh[1023];
}

__global__ void k_scatter(const int* __restrict__ src, const int* __restrict__ dst,
                          const int* __restrict__ rowptr, int* __restrict__ cursor,
                          int* __restrict__ csr) {
    int e = blockIdx.x * blockDim.x + threadIdx.x;
    if (e >= NE) return;
    int d = dst[e];
    int p = atomicAdd(&cursor[d], 1);
    csr[rowptr[d] + p] = src[e];
}

__global__ void k_split(const float* __restrict__ in,
                        __nv_bfloat16* __restrict__ hi, __nv_bfloat16* __restrict__ lo,
                        int rows, int Kin, int Kpad) {
    int idx = blockIdx.x * blockDim.x + threadIdx.x;
    int total = rows * Kpad;
    int stride = gridDim.x * blockDim.x;
    for (; idx < total; idx += stride) {
        int r = idx / Kpad;
        int c = idx - r * Kpad;
        float v = (c < Kin) ? in[(size_t)r * Kin + c] : 0.f;
        __nv_bfloat16 h = __float2bfloat16_rn(v);
        hi[idx] = h;
        lo[idx] = __float2bfloat16_rn(v - __bfloat162float(h));
    }
}

#define NSEG 10
struct WSeg { const float* in; int rows, Kin, Kpad, start; };
struct WSegs { WSeg s[NSEG]; int total; };

__global__ void k_split_all(WSegs segs, __nv_bfloat16* __restrict__ hi,
                            __nv_bfloat16* __restrict__ lo) {
    int idx = blockIdx.x * blockDim.x + threadIdx.x;
    int stride = gridDim.x * blockDim.x;
    for (; idx < segs.total; idx += stride) {
        int si = 0;
#pragma unroll
        for (int k = 1; k < NSEG; k++)
            if (idx >= segs.s[k].start) si = k;
        int li = idx - segs.s[si].start;
        int Kpad = segs.s[si].Kpad;
        int r = li / Kpad;
        int c = li - r * Kpad;
        float v = (c < segs.s[si].Kin)
                    ? segs.s[si].in[(size_t)r * segs.s[si].Kin + c] : 0.f;
        __nv_bfloat16 h = __float2bfloat16_rn(v);
        hi[idx] = h;
        lo[idx] = __float2bfloat16_rn(v - __bfloat162float(h));
    }
}

// ---------------- CSR aggregation (column-phased for L2 residency) ----------
__device__ __forceinline__ void addb4(float4& a, uint2 u) {
    __nv_bfloat162 p0 = *reinterpret_cast<__nv_bfloat162*>(&u.x);
    __nv_bfloat162 p1 = *reinterpret_cast<__nv_bfloat162*>(&u.y);
    a.x += __low2float(p0); a.y += __high2float(p0);
    a.z += __low2float(p1); a.w += __high2float(p1);
}

__global__ __launch_bounds__(64)
void k_aggcsr512p(const __nv_bfloat16* __restrict__ xh, const __nv_bfloat16* __restrict__ xl,
                  const int* __restrict__ rowptr, const int* __restrict__ csr,
                  __nv_bfloat16* __restrict__ ah, __nv_bfloat16* __restrict__ al) {
    int node = blockIdx.x;
    int c = blockIdx.y * 256 + threadIdx.x * 4;
    int start = __ldg(&rowptr[node]);
    int end = __ldg(&rowptr[node + 1]);
    float4 acc = make_float4(0.f, 0.f, 0.f, 0.f);
    int j = start;
    for (; j + 1 < end; j += 2) {
        int s0 = __ldg(&csr[j]);
        int s1 = __ldg(&csr[j + 1]);
        uint2 h0 = *(const uint2*)(xh + (size_t)s0 * HD + c);
        uint2 l0 = *(const uint2*)(xl + (size_t)s0 * HD + c);
        uint2 h1 = *(const uint2*)(xh + (size_t)s1 * HD + c);
        uint2 l1 = *(const uint2*)(xl + (size_t)s1 * HD + c);
        addb4(acc, h0); addb4(acc, l0);
        addb4(acc, h1); addb4(acc, l1);
    }
    if (j < end) {
        int s0 = __ldg(&csr[j]);
        uint2 h0 = *(const uint2*)(xh + (size_t)s0 * HD + c);
        uint2 l0 = *(const uint2*)(xl + (size_t)s0 * HD + c);
        addb4(acc, h0); addb4(acc, l0);
    }
    float inv = 1.0f / fmaxf((float)(end - start), 1.0f);
    acc.x *= inv; acc.y *= inv; acc.z *= inv; acc.w *= inv;
    __nv_bfloat162 h01, h23, l01, l23;
    h01.x = __float2bfloat16_rn(acc.x); h01.y = __float2bfloat16_rn(acc.y);
    h23.x = __float2bfloat16_rn(acc.z); h23.y = __float2bfloat16_rn(acc.w);
    l01.x = __float2bfloat16_rn(acc.x - __bfloat162float(h01.x));
    l01.y = __float2bfloat16_rn(acc.y - __bfloat162float(h01.y));
    l23.x = __float2bfloat16_rn(acc.z - __bfloat162float(h23.x));
    l23.y = __float2bfloat16_rn(acc.w - __bfloat162float(h23.y));
    uint2 hv, lv;
    memcpy(&hv.x, &h01, 4); memcpy(&hv.y, &h23, 4);
    memcpy(&lv.x, &l01, 4); memcpy(&lv.y, &l23, 4);
    __stcs((uint2*)(ah + (size_t)node * HD + c), hv);
    __stcs((uint2*)(al + (size_t)node * HD + c), lv);
}

__global__ __launch_bounds__(64)
void k_aggcsr50(const float* __restrict__ x,
                const int* __restrict__ rowptr, const int* __restrict__ csr,
                __nv_bfloat16* __restrict__ ah, __nv_bfloat16* __restrict__ al) {
    int node = blockIdx.x;
    int c = threadIdx.x;
    int start = __ldg(&rowptr[node]);
    int end = __ldg(&rowptr[node + 1]);
    float acc = 0.f;
    if (c < FD) {
        for (int j = start; j < end; j++) {
            int s = __ldg(&csr[j]);
            acc += __ldg(&x[(size_t)s * FD + c]);
        }
    }
    float inv = 1.0f / fmaxf((float)(end - start), 1.0f);
    float v = acc * inv;
    __nv_bfloat16 h = __float2bfloat16_rn(v);
    ah[(size_t)node * FDP + c] = h;
    al[(size_t)node * FDP + c] = __float2bfloat16_rn(v - __bfloat162float(h));
}

// ---------------- tensor-core dual GEMM + fused GraphNorm stats -------------
#define GBM 128
#define GBN 128
#define GBK 32
#define ASTRIDE 40
#define TILE_B (GBM * ASTRIDE * 2)
#define BUF_B (4 * TILE_B)
#define GEMM_DYN (2 * BUF_B)

#define LDM_X4(r0_, r1_, r2_, r3_, addr_)                                        \
    asm volatile("ldmatrix.sync.aligned.m8n8.x4.shared.b16 {%0,%1,%2,%3}, [%4];" \
                 : "=r"(r0_), "=r"(r1_), "=r"(r2_), "=r"(r3_) : "r"(addr_))

#define MMA16816(c_, a_, b_)                                                   \
    asm volatile("mma.sync.aligned.m16n8k16.row.col.f32.bf16.bf16.f32 "        \
                 "{%0,%1,%2,%3}, {%4,%5,%6,%7}, {%8,%9}, {%0,%1,%2,%3};"       \
                 : "+f"(c_[0]), "+f"(c_[1]), "+f"(c_[2]), "+f"(c_[3])          \
                 : "r"(a_[0]), "r"(a_[1]), "r"(a_[2]), "r"(a_[3]),             \
                   "r"(b_[0]), "r"(b_[1]))

__device__ __forceinline__ void cp16(uint32_t dst, const void* src, int okbytes) {
    asm volatile("cp.async.cg.shared.global [%0], [%1], 16, %2;"
                 :: "r"(dst), "l"(src), "r"(okbytes));
}

__device__ __forceinline__ void load_block4(const __nv_bfloat16* AH, const __nv_bfloat16* AL,
                                            const __nv_bfloat16* WH, const __nv_bfloat16* WL,
                                            int rbase, int cbase, int kb, int K,
                                            int Nr, int M, uint32_t sb) {
    int t = threadIdx.x;
#pragma unroll
    for (int p = 0; p < 8; p++) {
        int idx = t + p * 256;
        int tile = idx >> 9;
        int i9 = idx & 511;
        int row = i9 >> 2;
        int seg = i9 & 3;
        uint32_t soff = sb + (uint32_t)tile * TILE_B + (uint32_t)(row * ASTRIDE + seg * 8) * 2;
        const __nv_bfloat16* base;
        int gr, lim;
        if (tile < 2) { gr = rbase + row; lim = Nr; base = tile ? AL : AH; }
        else          { gr = cbase + row; lim = M;  base = (tile == 2) ? WH : WL; }
        int ok = (gr < lim) ? 16 : 0;
        int gg = (gr < lim) ? gr : 0;
        cp16(soff, base + (size_t)gg * K + kb + seg * 8, ok);
    }
}

__global__ __launch_bounds__(256, 2)
void k_gemm_tc(const __nv_bfloat16* __restrict__ Ah1, const __nv_bfloat16* __restrict__ Al1,
               const __nv_bfloat16* __restrict__ Wh1, const __nv_bfloat16* __restrict__ Wl1,
               const __nv_bfloat16* __restrict__ Ah2, const __nv_bfloat16* __restrict__ Al2,
               const __nv_bfloat16* __restrict__ Wh2, const __nv_bfloat16* __restrict__ Wl2,
               const float* __restrict__ bias, float* __restrict__ C,
               const int* __restrict__ batch, float* __restrict__ gsum,
               float* __restrict__ gsq, int doStats,
               int Nr, int M, int K) {
    extern __shared__ __align__(16) char dyn[];
    uint32_t sbase = (uint32_t)__cvta_generic_to_shared(dyn);

    int t = threadIdx.x;
    int lane = t & 31;
    int wid = t >> 5;
    int wm = (wid >> 2) * 64;
    int wn = (wid & 3) * 32;
    int rbase = blockIdx.y * GBM;
    int cbase = blockIdx.x * GBN;

    float acc[4][4][4];
#pragma unroll
    for (int i = 0; i < 4; i++)
#pragma unroll
        for (int j = 0; j < 4; j++)
#pragma unroll
            for (int q = 0; q < 4; q++) acc[i][j][q] = 0.f;

    const int KB = K / GBK;
    const int total = 2 * KB;

    auto pick = [&](int blk, const __nv_bfloat16*& AH, const __nv_bfloat16*& AL,
                    const __nv_bfloat16*& WH, const __nv_bfloat16*& WL, int& kb) {
        int pass = blk / KB;
        kb = (blk - pass * KB) * GBK;
        if (pass == 0) { AH = Ah1; AL = Al1; WH = Wh1; WL = Wl1; }
        else           { AH = Ah2; AL = Al2; WH = Wh2; WL = Wl2; }
    };

    int g = lane >> 3;
    int rA = (lane & 7) + ((g & 1) << 3);
    int kA = (g >> 1) << 3;
    int rB = (lane & 7) + ((g >> 1) << 3);
    int kB = (g & 1) << 3;

    {
        const __nv_bfloat16 *AH, *AL, *WH, *WL; int kb;
        pick(0, AH, AL, WH, WL, kb);
        load_block4(AH, AL, WH, WL, rbase, cbase, kb, K, Nr, M, sbase);
        asm volatile("cp.async.commit_group;");
    }

    for (int it = 0; it < total; it++) {
        if (it + 1 < total) {
            const __nv_bfloat16 *AH, *AL, *WH, *WL; int kb;
            pick(it + 1, AH, AL, WH, WL, kb);
            load_block4(AH, AL, WH, WL, rbase, cbase, kb, K, Nr, M,
                        sbase + ((it + 1) & 1) * BUF_B);
            asm volatile("cp.async.commit_group;");
            asm volatile("cp.async.wait_group 1;");
        } else {
            asm volatile("cp.async.wait_group 0;");
        }
        __syncthreads();

        uint32_t buf = sbase + (it & 1) * BUF_B;
        uint32_t bAh = buf;
        uint32_t bAl = buf + TILE_B;
        uint32_t bWh = buf + 2 * TILE_B;
        uint32_t bWl = buf + 3 * TILE_B;
#pragma unroll
        for (int s = 0; s < 2; s++) {
            uint32_t ahf[4][4];
#pragma unroll
            for (int mt = 0; mt < 4; mt++) {
                uint32_t addr = bAh + (uint32_t)((wm + mt * 16 + rA) * ASTRIDE + s * 16 + kA) * 2;
                LDM_X4(ahf[mt][0], ahf[mt][1], ahf[mt][2], ahf[mt][3], addr);
            }
            uint32_t bh[4][2];
#pragma unroll
            for (int np = 0; np < 2; np++) {
                uint32_t addr = bWh + (uint32_t)((wn + np * 16 + rB) * ASTRIDE + s * 16 + kB) * 2;
                uint32_t q0, q1, q2, q3;
                LDM_X4(q0, q1, q2, q3, addr);
                bh[np * 2][0] = q0; bh[np * 2][1] = q1;
                bh[np * 2 + 1][0] = q2; bh[np * 2 + 1][1] = q3;
            }
#pragma unroll
            for (int mt = 0; mt < 4; mt++)
#pragma unroll
                for (int nt = 0; nt < 4; nt++) MMA16816(acc[mt][nt], ahf[mt], bh[nt]);
            uint32_t bl[4][2];
#pragma unroll
            for (int np = 0; np < 2; np++) {
                uint32_t addr = bWl + (uint32_t)((wn + np * 16 + rB) * ASTRIDE + s * 16 + kB) * 2;
                uint32_t q0, q1, q2, q3;
                LDM_X4(q0, q1, q2, q3, addr);
                bl[np * 2][0] = q0; bl[np * 2][1] = q1;
                bl[np * 2 + 1][0] = q2; bl[np * 2 + 1][1] = q3;
            }
#pragma unroll
            for (int mt = 0; mt < 4; mt++)
#pragma unroll
                for (int nt = 0; nt < 4; nt++) MMA16816(acc[mt][nt], ahf[mt], bl[nt]);
            uint32_t alf[4][4];
#pragma unroll
            for (int mt = 0; mt < 4; mt++) {
                uint32_t addr = bAl + (uint32_t)((wm + mt * 16 + rA) * ASTRIDE + s * 16 + kA) * 2;
                LDM_X4(alf[mt][0], alf[mt][1], alf[mt][2], alf[mt][3], addr);
            }
#pragma unroll
            for (int mt = 0; mt < 4; mt++)
#pragma unroll
                for (int nt = 0; nt < 4; nt++) MMA16816(acc[mt][nt], alf[mt], bh[nt]);
        }
        __syncthreads();
    }

    // ---- epilogue: bias + store + (optional) fused GraphNorm stats ----
    float* ssum = (float*)dyn;          // [2][128]
    float* ssq  = (float*)dyn + 256;    // [2][128]
    int gBase = 0;
    if (doStats) {
        for (int i = t; i < 512; i += 256) ((float*)dyn)[i] = 0.f;
        gBase = __ldg(&batch[rbase < Nr ? rbase : (Nr - 1)]);
        __syncthreads();
    }

#pragma unroll
    for (int mt = 0; mt < 4; mt++) {
        int row0 = rbase + wm + mt * 16 + (lane >> 2);
        int row1 = row0 + 8;
#pragma unroll
        for (int nt = 0; nt < 4; nt++) {
            int col0 = cbase + wn + nt * 8 + (lane & 3) * 2;
            int cl0 = wn + nt * 8 + (lane & 3) * 2;
            if (col0 < M) {
                float b0 = bias[col0];
                if (row0 < Nr) {
                    float v = acc[mt][nt][0] + b0;
                    C[(size_t)row0 * M + col0] = v;
                    if (doStats) {
                        int gl = __ldg(&batch[row0]) - gBase;
                        if (gl <= 1) {
                            atomicAdd(&ssum[gl * 128 + cl0], v);
                            atomicAdd(&ssq[gl * 128 + cl0], v * v);
                        } else {
                            atomicAdd(&gsum[(gBase + gl) * HD + col0], v);
                            atomicAdd(&gsq[(gBase + gl) * HD + col0], v * v);
                        }
                    }
                }
                if (row1 < Nr) {
                    float v = acc[mt][nt][2] + b0;
                    C[(size_t)row1 * M + col0] = v;
                    if (doStats) {
                        int gl = __ldg(&batch[row1]) - gBase;
                        if (gl <= 1) {
                            atomicAdd(&ssum[gl * 128 + cl0], v);
                            atomicAdd(&ssq[gl * 128 + cl0], v * v);
                        } else {
                            atomicAdd(&gsum[(gBase + gl) * HD + col0], v);
                            atomicAdd(&gsq[(gBase + gl) * HD + col0], v * v);
                        }
                    }
                }
            }
            if (col0 + 1 < M) {
                float b1 = bias[col0 + 1];
                if (row0 < Nr) {
                    float v = acc[mt][nt][1] + b1;
                    C[(size_t)row0 * M + col0 + 1] = v;
                    if (doStats) {
                        int gl = __ldg(&batch[row0]) - gBase;
                        if (gl <= 1) {
                            atomicAdd(&ssum[gl * 128 + cl0 + 1], v);
                            atomicAdd(&ssq[gl * 128 + cl0 + 1], v * v);
                        } else {
                            atomicAdd(&gsum[(gBase + gl) * HD + col0 + 1], v);
                            atomicAdd(&gsq[(gBase + gl) * HD + col0 + 1], v * v);
                        }
                    }
                }
                if (row1 < Nr) {
                    float v = acc[mt][nt][3] + b1;
                    C[(size_t)row1 * M + col0 + 1] = v;
                    if (doStats) {
                        int gl = __ldg(&batch[row1]) - gBase;
                        if (gl <= 1) {
                            atomicAdd(&ssum[gl * 128 + cl0 + 1], v);
                            atomicAdd(&ssq[gl * 128 + cl0 + 1], v * v);
                        } else {
                            atomicAdd(&gsum[(gBase + gl) * HD + col0 + 1], v);
                            atomicAdd(&gsq[(gBase + gl) * HD + col0 + 1], v * v);
                        }
                    }
                }
            }
        }
    }

    if (doStats) {
        __syncthreads();
        // flush 2 groups x 128 cols; one entry per thread
        int gl = t >> 7, cl = t & 127;
        int gg = gBase + gl;
        if (gg < NG) {
            float s = ssum[gl * 128 + cl];
            float q = ssq[gl * 128 + cl];
            if (s != 0.f || q != 0.f) {
                atomicAdd(&gsum[gg * HD + cbase + cl], s);
                atomicAdd(&gsq[gg * HD + cbase + cl], q);
            }
        }
    }
}

// ---------------- GraphNorm coef + apply ------------------------------------
// coef also zeroes gsum/gsq after reading (ready for next fused-stats GEMM)
__global__ void k_gn_coef(float* __restrict__ gsum, float* __restrict__ gsq,
                          const float* __restrict__ invsz,
                          const float* __restrict__ w, const float* __restrict__ b,
                          const float* __restrict__ a,
                          float* __restrict__ gS, float* __restrict__ gT) {
    int i = blockIdx.x * blockDim.x + threadIdx.x;
    if (i >= NG * HD) return;
    int g = i / HD, c = i - g * HD;
    float iv = invsz[g];
    float m = gsum[i] * iv;
    float e2 = gsq[i] * iv;
    gsum[i] = 0.f;
    gsq[i] = 0.f;
    float alc = a[c];
    float var = e2 - alc * (2.f - alc) * m * m;
    float S = rsqrtf(var + EPSV) * w[c];
    gS[i] = S;
    gT[i] = b[c] - alc * m * S;
}

__global__ void k_gn_apply2(const float* __restrict__ h, const int* __restrict__ batch,
                            const float* __restrict__ gS, const float* __restrict__ gT,
                            __nv_bfloat16* __restrict__ xh, __nv_bfloat16* __restrict__ xl) {
    int i4 = blockIdx.x * blockDim.x + threadIdx.x;
    const int n4 = NN * (HD / 4);
    if (i4 >= n4) return;
    int r = i4 >> 7;
    int c4 = (i4 & 127) * 4;
    int g = batch[r];
    float4 v = *((const float4*)h + i4);
    float4 S = *(const float4*)&gS[g * HD + c4];
    float4 T = *(const float4*)&gT[g * HD + c4];
    v.x = fmaxf(fmaf(v.x, S.x, T.x), 0.f);
    v.y = fmaxf(fmaf(v.y, S.y, T.y), 0.f);
    v.z = fmaxf(fmaf(v.z, S.z, T.z), 0.f);
    v.w = fmaxf(fmaf(v.w, S.w, T.w), 0.f);
    __nv_bfloat162 h01, h23, l01, l23;
    h01.x = __float2bfloat16_rn(v.x); h01.y = __float2bfloat16_rn(v.y);
    h23.x = __float2bfloat16_rn(v.z); h23.y = __float2bfloat16_rn(v.w);
    l01.x = __float2bfloat16_rn(v.x - __bfloat162float(h01.x));
    l01.y = __float2bfloat16_rn(v.y - __bfloat162float(h01.y));
    l23.x = __float2bfloat16_rn(v.z - __bfloat162float(h23.x));
    l23.y = __float2bfloat16_rn(v.w - __bfloat162float(h23.y));
    *(__nv_bfloat162*)(xh + (size_t)i4 * 4) = h01;
    *(__nv_bfloat162*)(xh + (size_t)i4 * 4 + 2) = h23;
    *(__nv_bfloat162*)(xl + (size_t)i4 * 4) = l01;
    *(__nv_bfloat162*)(xl + (size_t)i4 * 4 + 2) = l23;
}

// ---------------- host-side orchestration ----------------------------------
static float* symaddrf(const void* s) { void* p = nullptr; cudaGetSymbolAddress(&p, s); return (float*)p; }
static int* symaddri(const void* s) { void* p = nullptr; cudaGetSymbolAddress(&p, s); return (int*)p; }
static __nv_bfloat16* symaddrb(const void* s) { void* p = nullptr; cudaGetSymbolAddress(&p, s); return (__nv_bfloat16*)p; }

extern "C" void kernel_launch(void* const* d_in, const int* in_sizes, int n_in,
                              void* d_out, int out_size) {
    const float* x      = (const float*)d_in[0];
    const int*   ei     = (const int*)d_in[1];
    const int*   batch  = (const int*)d_in[2];
    const int*   src    = ei;
    const int*   dst    = ei + NE;

    const float* Wl[5] = {(const float*)d_in[3], (const float*)d_in[6], (const float*)d_in[9],
                          (const float*)d_in[12], (const float*)d_in[15]};
    const float* Wr[5] = {(const float*)d_in[4], (const float*)d_in[7], (const float*)d_in[10],
                          (const float*)d_in[13], (const float*)d_in[16]};
    const float* bb[5] = {(const float*)d_in[5], (const float*)d_in[8], (const float*)d_in[11],
                          (const float*)d_in[14], (const float*)d_in[17]};
    const float* gw[4] = {(const float*)d_in[18], (const float*)d_in[21], (const float*)d_in[24],
                          (const float*)d_in[27]};
    const float* gb_[4] = {(const float*)d_in[19], (const float*)d_in[22], (const float*)d_in[25],
                           (const float*)d_in[28]};
    const float* ga[4] = {(const float*)d_in[20], (const float*)d_in[23], (const float*)d_in[26],
                          (const float*)d_in[29]};

    float* h1     = symaddrf(g_h1);
    int*   degi   = symaddri(g_degi);
    int*   rowptr = symaddri(g_rowptr);
    int*   cursor = symaddri(g_cursor);
    int*   csr    = symaddri(g_csr);
    float* invsz  = symaddrf(g_invsz);
    float* gsum   = symaddrf(g_gsum);
    float* gsq    = symaddrf(g_gsq);
    float* gS     = symaddrf(g_gS);
    float* gT     = symaddrf(g_gT);
    __nv_bfloat16* ah = symaddrb(g_ah);
    __nv_bfloat16* al = symaddrb(g_al);
    __nv_bfloat16* xh = symaddrb(g_xh);
    __nv_bfloat16* xl = symaddrb(g_xl);
    __nv_bfloat16* wh = symaddrb(g_wh);
    __nv_bfloat16* wl = symaddrb(g_wl);

    cudaFuncSetAttribute(k_gemm_tc, cudaFuncAttributeMaxDynamicSharedMemorySize, GEMM_DYN);

    int wrows[5] = {HD, HD, HD, HD, OD};
    int wkin[5]  = {FD, HD, HD, HD, HD};
    int wkpad[5] = {FDP, HD, HD, HD, HD};
    WSegs segs;
    int off = 0;
    int offl[5], offr[5];
    for (int l = 0; l < 5; l++) {
        offl[l] = off;
        segs.s[2 * l] = {Wl[l], wrows[l], wkin[l], wkpad[l], off};
        off += wrows[l] * wkpad[l];
        offr[l] = off;
        segs.s[2 * l + 1] = {Wr[l], wrows[l], wkin[l], wkpad[l], off};
        off += wrows[l] * wkpad[l];
    }
    segs.total = off;   // == WTOT

    auto GEMM = [&](int l, const float* bias, float* C, int Mout, int K, int doStats) {
        dim3 grid((Mout + GBN - 1) / GBN, (NN + GBM - 1) / GBM);
        k_gemm_tc<<<grid, 256, GEMM_DYN>>>(ah, al, wh + offl[l], wl + offl[l],
                                           xh, xl, wh + offr[l], wl + offr[l],
                                           bias, C, batch, gsum, gsq, doStats,
                                           NN, Mout, K);
    };

    // ---- CSR build + group sizes + weight splits + stats buffers ----
    k_zero2i<<<(NN + 255) / 256, 256>>>(degi, cursor, NN);
    k_zero2f<<<(NG * HD + 255) / 256, 256>>>(gsum, gsq, NG * HD);
    k_count_i<<<(NE + 255) / 256, 256>>>(dst, degi, NE);
    k_scan2<<<1, 1024>>>(degi, rowptr);
    k_scatter<<<(NE + 255) / 256, 256>>>(src, dst, rowptr, cursor, csr);
    k_group_sizes<<<1, 32>>>(batch, invsz);
    k_split_all<<<(WTOT + 255) / 256, 256>>>(segs, wh, wl);

    auto gnorm = [&](float* h, const float* w, const float* bias, const float* alpha) {
        k_gn_coef<<<(NG * HD + 255) / 256, 256>>>(gsum, gsq, invsz, w, bias, alpha, gS, gT);
        k_gn_apply2<<<(NN * (HD / 4) + 255) / 256, 256>>>(h, batch, gS, gT, xh, xl);
    };

    // ---- layer 1 (50 -> 512) ----
    k_aggcsr50<<<NN, 64>>>(x, rowptr, csr, ah, al);
    k_split<<<(NN * FDP + 255) / 256 > 65535 ? 65535 : (NN * FDP + 255) / 256, 256>>>(
        x, xh, xl, NN, FD, FDP);
    GEMM(0, bb[0], h1, HD, FDP, 1);
    gnorm(h1, gw[0], gb_[0], ga[0]);

    // ---- layers 2..4 (512 -> 512) ----
    for (int l = 1; l <= 3; l++) {
        k_aggcsr512p<<<dim3(NN, 2), 64>>>(xh, xl, rowptr, csr, ah, al);
        GEMM(l, bb[l], h1, HD, HD, 1);
        gnorm(h1, gw[l], gb_[l], ga[l]);
    }

    // ---- layer 5 (512 -> 121) -> d_out ----
    k_aggcsr512p<<<dim3(NN, 2), 64>>>(xh, xl, rowptr, csr, ah, al);
    GEMM(4, bb[4], (float*)d_out, OD, HD, 0);
}

// round 17
// speedup vs baseline: 2.3612x; 2.3612x over previous
#include <cuda_runtime.h>
#include <cuda_bf16.h>
#include <cstdint>
#include <math.h>

#define NN 50000
#define NE 800000
#define FD 50
#define FDP 64
#define HD 512
#define OD 121
#define NG 20
#define EPSV 1e-5f

// ---------------- scratch ---------------------------------------------------
__device__ float g_h1[(size_t)NN * HD];
__device__ int   g_degi[NN];
__device__ int   g_rowptr[NN + 1];
__device__ int   g_cursor[NN];
__device__ int   g_csr[NE];
__device__ float g_invsz[NG];
__device__ float g_gsum[NG * HD];
__device__ float g_gsq[NG * HD];
__device__ float g_gS[NG * HD];
__device__ float g_gT[NG * HD];
__device__ __nv_bfloat16 g_ah[(size_t)NN * HD];
__device__ __nv_bfloat16 g_al[(size_t)NN * HD];
__device__ __nv_bfloat16 g_xh[(size_t)NN * HD];
__device__ __nv_bfloat16 g_xl[(size_t)NN * HD];
#define WTOT 1762304
__device__ __nv_bfloat16 g_wh[WTOT];
__device__ __nv_bfloat16 g_wl[WTOT];

// ---------------- utility ---------------------------------------------------
__global__ void k_zero2f(float* __restrict__ a, float* __restrict__ b, int n) {
    int i = blockIdx.x * blockDim.x + threadIdx.x;
    if (i < n) { a[i] = 0.f; b[i] = 0.f; }
}

__global__ void k_zero2i(int* __restrict__ a, int* __restrict__ b, int n) {
    int i = blockIdx.x * blockDim.x + threadIdx.x;
    if (i < n) { a[i] = 0; b[i] = 0; }
}

__global__ void k_count_i(const int* __restrict__ idx, int* __restrict__ cnt, int n) {
    int i = blockIdx.x * blockDim.x + threadIdx.x;
    if (i < n) atomicAdd(&cnt[idx[i]], 1);
}

__global__ void k_group_sizes(const int* __restrict__ batch, float* __restrict__ invsz) {
    int g = threadIdx.x;
    if (g >= NG) return;
    int lo = 0, hi = NN;
    while (lo < hi) { int m = (lo + hi) >> 1; if (batch[m] < g) lo = m + 1; else hi = m; }
    int lb = lo;
    lo = 0; hi = NN;
    while (lo < hi) { int m = (lo + hi) >> 1; if (batch[m] < g + 1) lo = m + 1; else hi = m; }
    invsz[g] = 1.0f / fmaxf((float)(lo - lb), 1.0f);
}

// staged scan: deg chunks staged through smem (coalesced), then block scan
#define SCH 10240
__global__ void k_scan2(const int* __restrict__ deg, int* __restrict__ rowptr) {
    __shared__ int sdeg[SCH];
    __shared__ int sh[1024];
    int tid = threadIdx.x;
    const int CH = (NN + 1023) / 1024;   // 49
    int start = tid * CH, end = min(start + CH, NN);
    int s = 0;
    for (int base = 0; base < NN; base += SCH) {
        int lim = min(SCH, NN - base);
        __syncthreads();
        for (int i = tid; i < lim; i += 1024) sdeg[i] = deg[base + i];
        __syncthreads();
        int lo = max(start, base), hiX = min(end, base + lim);
        for (int i = lo; i < hiX; i++) s += sdeg[i - base];
    }
    sh[tid] = s;
    __syncthreads();
    for (int d = 1; d < 1024; d <<= 1) {
        int v = (tid >= d) ? sh[tid - d] : 0;
        __syncthreads();
        sh[tid] += v;
        __syncthreads();
    }
    int off = sh[tid] - s;
    for (int i = start; i < end; i++) { rowptr[i] = off; off += deg[i]; }
    if (tid == 1023) rowptr[NN] = sh[1023];
}

__global__ void k_scatter(const int* __restrict__ src, const int* __restrict__ dst,
                          const int* __restrict__ rowptr, int* __restrict__ cursor,
                          int* __restrict__ csr) {
    int e = blockIdx.x * blockDim.x + threadIdx.x;
    if (e >= NE) return;
    int d = dst[e];
    int p = atomicAdd(&cursor[d], 1);
    csr[rowptr[d] + p] = src[e];
}

__global__ void k_split(const float* __restrict__ in,
                        __nv_bfloat16* __restrict__ hi, __nv_bfloat16* __restrict__ lo,
                        int rows, int Kin, int Kpad) {
    int idx = blockIdx.x * blockDim.x + threadIdx.x;
    int total = rows * Kpad;
    int stride = gridDim.x * blockDim.x;
    for (; idx < total; idx += stride) {
        int r = idx / Kpad;
        int c = idx - r * Kpad;
        float v = (c < Kin) ? in[(size_t)r * Kin + c] : 0.f;
        __nv_bfloat16 h = __float2bfloat16_rn(v);
        hi[idx] = h;
        lo[idx] = __float2bfloat16_rn(v - __bfloat162float(h));
    }
}

#define NSEG 10
struct WSeg { const float* in; int rows, Kin, Kpad, start; };
struct WSegs { WSeg s[NSEG]; int total; };

__global__ void k_split_all(WSegs segs, __nv_bfloat16* __restrict__ hi,
                            __nv_bfloat16* __restrict__ lo) {
    int idx = blockIdx.x * blockDim.x + threadIdx.x;
    int stride = gridDim.x * blockDim.x;
    for (; idx < segs.total; idx += stride) {
        int si = 0;
#pragma unroll
        for (int k = 1; k < NSEG; k++)
            if (idx >= segs.s[k].start) si = k;
        int li = idx - segs.s[si].start;
        int Kpad = segs.s[si].Kpad;
        int r = li / Kpad;
        int c = li - r * Kpad;
        float v = (c < segs.s[si].Kin)
                    ? segs.s[si].in[(size_t)r * segs.s[si].Kin + c] : 0.f;
        __nv_bfloat16 h = __float2bfloat16_rn(v);
        hi[idx] = h;
        lo[idx] = __float2bfloat16_rn(v - __bfloat162float(h));
    }
}

// ---------------- CSR aggregation (column-phased for L2 residency) ----------
__device__ __forceinline__ void addb4(float4& a, uint2 u) {
    __nv_bfloat162 p0 = *reinterpret_cast<__nv_bfloat162*>(&u.x);
    __nv_bfloat162 p1 = *reinterpret_cast<__nv_bfloat162*>(&u.y);
    a.x += __low2float(p0); a.y += __high2float(p0);
    a.z += __low2float(p1); a.w += __high2float(p1);
}

__global__ __launch_bounds__(64)
void k_aggcsr512p(const __nv_bfloat16* __restrict__ xh, const __nv_bfloat16* __restrict__ xl,
                  const int* __restrict__ rowptr, const int* __restrict__ csr,
                  __nv_bfloat16* __restrict__ ah, __nv_bfloat16* __restrict__ al) {
    int node = blockIdx.x;
    int c = blockIdx.y * 256 + threadIdx.x * 4;
    int start = __ldg(&rowptr[node]);
    int end = __ldg(&rowptr[node + 1]);
    float4 acc = make_float4(0.f, 0.f, 0.f, 0.f);
    int j = start;
    for (; j + 1 < end; j += 2) {
        int s0 = __ldg(&csr[j]);
        int s1 = __ldg(&csr[j + 1]);
        uint2 h0 = *(const uint2*)(xh + (size_t)s0 * HD + c);
        uint2 l0 = *(const uint2*)(xl + (size_t)s0 * HD + c);
        uint2 h1 = *(const uint2*)(xh + (size_t)s1 * HD + c);
        uint2 l1 = *(const uint2*)(xl + (size_t)s1 * HD + c);
        addb4(acc, h0); addb4(acc, l0);
        addb4(acc, h1); addb4(acc, l1);
    }
    if (j < end) {
        int s0 = __ldg(&csr[j]);
        uint2 h0 = *(const uint2*)(xh + (size_t)s0 * HD + c);
        uint2 l0 = *(const uint2*)(xl + (size_t)s0 * HD + c);
        addb4(acc, h0); addb4(acc, l0);
    }
    float inv = 1.0f / fmaxf((float)(end - start), 1.0f);
    acc.x *= inv; acc.y *= inv; acc.z *= inv; acc.w *= inv;
    __nv_bfloat162 h01, h23, l01, l23;
    h01.x = __float2bfloat16_rn(acc.x); h01.y = __float2bfloat16_rn(acc.y);
    h23.x = __float2bfloat16_rn(acc.z); h23.y = __float2bfloat16_rn(acc.w);
    l01.x = __float2bfloat16_rn(acc.x - __bfloat162float(h01.x));
    l01.y = __float2bfloat16_rn(acc.y - __bfloat162float(h01.y));
    l23.x = __float2bfloat16_rn(acc.z - __bfloat162float(h23.x));
    l23.y = __float2bfloat16_rn(acc.w - __bfloat162float(h23.y));
    uint2 hv, lv;
    memcpy(&hv.x, &h01, 4); memcpy(&hv.y, &h23, 4);
    memcpy(&lv.x, &l01, 4); memcpy(&lv.y, &l23, 4);
    __stcs((uint2*)(ah + (size_t)node * HD + c), hv);
    __stcs((uint2*)(al + (size_t)node * HD + c), lv);
}

__global__ __launch_bounds__(64)
void k_aggcsr50(const float* __restrict__ x,
                const int* __restrict__ rowptr, const int* __restrict__ csr,
                __nv_bfloat16* __restrict__ ah, __nv_bfloat16* __restrict__ al) {
    int node = blockIdx.x;
    int c = threadIdx.x;
    int start = __ldg(&rowptr[node]);
    int end = __ldg(&rowptr[node + 1]);
    float acc = 0.f;
    if (c < FD) {
        for (int j = start; j < end; j++) {
            int s = __ldg(&csr[j]);
            acc += __ldg(&x[(size_t)s * FD + c]);
        }
    }
    float inv = 1.0f / fmaxf((float)(end - start), 1.0f);
    float v = acc * inv;
    __nv_bfloat16 h = __float2bfloat16_rn(v);
    ah[(size_t)node * FDP + c] = h;
    al[(size_t)node * FDP + c] = __float2bfloat16_rn(v - __bfloat162float(h));
}

// ---------------- tensor-core dual GEMM (mma.sync, fragment reuse) ----------
#define GBM 128
#define GBN 128
#define GBK 32
#define ASTRIDE 40
#define TILE_B (GBM * ASTRIDE * 2)
#define BUF_B (4 * TILE_B)
#define GEMM_DYN (2 * BUF_B)

#define LDM_X4(r0_, r1_, r2_, r3_, addr_)                                        \
    asm volatile("ldmatrix.sync.aligned.m8n8.x4.shared.b16 {%0,%1,%2,%3}, [%4];" \
                 : "=r"(r0_), "=r"(r1_), "=r"(r2_), "=r"(r3_) : "r"(addr_))

#define MMA16816(c_, a_, b_)                                                   \
    asm volatile("mma.sync.aligned.m16n8k16.row.col.f32.bf16.bf16.f32 "        \
                 "{%0,%1,%2,%3}, {%4,%5,%6,%7}, {%8,%9}, {%0,%1,%2,%3};"       \
                 : "+f"(c_[0]), "+f"(c_[1]), "+f"(c_[2]), "+f"(c_[3])          \
                 : "r"(a_[0]), "r"(a_[1]), "r"(a_[2]), "r"(a_[3]),             \
                   "r"(b_[0]), "r"(b_[1]))

__device__ __forceinline__ void cp16(uint32_t dst, const void* src, int okbytes) {
    asm volatile("cp.async.cg.shared.global [%0], [%1], 16, %2;"
                 :: "r"(dst), "l"(src), "r"(okbytes));
}

__device__ __forceinline__ void load_block4(const __nv_bfloat16* AH, const __nv_bfloat16* AL,
                                            const __nv_bfloat16* WH, const __nv_bfloat16* WL,
                                            int rbase, int cbase, int kb, int K,
                                            int Nr, int M, uint32_t sb) {
    int t = threadIdx.x;
#pragma unroll
    for (int p = 0; p < 8; p++) {
        int idx = t + p * 256;
        int tile = idx >> 9;
        int i9 = idx & 511;
        int row = i9 >> 2;
        int seg = i9 & 3;
        uint32_t soff = sb + (uint32_t)tile * TILE_B + (uint32_t)(row * ASTRIDE + seg * 8) * 2;
        const __nv_bfloat16* base;
        int gr, lim;
        if (tile < 2) { gr = rbase + row; lim = Nr; base = tile ? AL : AH; }
        else          { gr = cbase + row; lim = M;  base = (tile == 2) ? WH : WL; }
        int ok = (gr < lim) ? 16 : 0;
        int gg = (gr < lim) ? gr : 0;
        cp16(soff, base + (size_t)gg * K + kb + seg * 8, ok);
    }
}

__global__ __launch_bounds__(256, 2)
void k_gemm_tc(const __nv_bfloat16* __restrict__ Ah1, const __nv_bfloat16* __restrict__ Al1,
               const __nv_bfloat16* __restrict__ Wh1, const __nv_bfloat16* __restrict__ Wl1,
               const __nv_bfloat16* __restrict__ Ah2, const __nv_bfloat16* __restrict__ Al2,
               const __nv_bfloat16* __restrict__ Wh2, const __nv_bfloat16* __restrict__ Wl2,
               const float* __restrict__ bias, float* __restrict__ C,
               int Nr, int M, int K) {
    extern __shared__ __align__(16) char dyn[];
    uint32_t sbase = (uint32_t)__cvta_generic_to_shared(dyn);

    int t = threadIdx.x;
    int lane = t & 31;
    int wid = t >> 5;
    int wm = (wid >> 2) * 64;
    int wn = (wid & 3) * 32;
    int rbase = blockIdx.y * GBM;
    int cbase = blockIdx.x * GBN;

    float acc[4][4][4];
#pragma unroll
    for (int i = 0; i < 4; i++)
#pragma unroll
        for (int j = 0; j < 4; j++)
#pragma unroll
            for (int q = 0; q < 4; q++) acc[i][j][q] = 0.f;

    const int KB = K / GBK;
    const int total = 2 * KB;

    auto pick = [&](int blk, const __nv_bfloat16*& AH, const __nv_bfloat16*& AL,
                    const __nv_bfloat16*& WH, const __nv_bfloat16*& WL, int& kb) {
        int pass = blk / KB;
        kb = (blk - pass * KB) * GBK;
        if (pass == 0) { AH = Ah1; AL = Al1; WH = Wh1; WL = Wl1; }
        else           { AH = Ah2; AL = Al2; WH = Wh2; WL = Wl2; }
    };

    int g = lane >> 3;
    int rA = (lane & 7) + ((g & 1) << 3);
    int kA = (g >> 1) << 3;
    int rB = (lane & 7) + ((g >> 1) << 3);
    int kB = (g & 1) << 3;

    {
        const __nv_bfloat16 *AH, *AL, *WH, *WL; int kb;
        pick(0, AH, AL, WH, WL, kb);
        load_block4(AH, AL, WH, WL, rbase, cbase, kb, K, Nr, M, sbase);
        asm volatile("cp.async.commit_group;");
    }

    for (int it = 0; it < total; it++) {
        if (it + 1 < total) {
            const __nv_bfloat16 *AH, *AL, *WH, *WL; int kb;
            pick(it + 1, AH, AL, WH, WL, kb);
            load_block4(AH, AL, WH, WL, rbase, cbase, kb, K, Nr, M,
                        sbase + ((it + 1) & 1) * BUF_B);
            asm volatile("cp.async.commit_group;");
            asm volatile("cp.async.wait_group 1;");
        } else {
            asm volatile("cp.async.wait_group 0;");
        }
        __syncthreads();

        uint32_t buf = sbase + (it & 1) * BUF_B;
        uint32_t bAh = buf;
        uint32_t bAl = buf + TILE_B;
        uint32_t bWh = buf + 2 * TILE_B;
        uint32_t bWl = buf + 3 * TILE_B;
#pragma unroll
        for (int s = 0; s < 2; s++) {
            uint32_t ahf[4][4];
#pragma unroll
            for (int mt = 0; mt < 4; mt++) {
                uint32_t addr = bAh + (uint32_t)((wm + mt * 16 + rA) * ASTRIDE + s * 16 + kA) * 2;
                LDM_X4(ahf[mt][0], ahf[mt][1], ahf[mt][2], ahf[mt][3], addr);
            }
            uint32_t bh[4][2];
#pragma unroll
            for (int np = 0; np < 2; np++) {
                uint32_t addr = bWh + (uint32_t)((wn + np * 16 + rB) * ASTRIDE + s * 16 + kB) * 2;
                uint32_t q0, q1, q2, q3;
                LDM_X4(q0, q1, q2, q3, addr);
                bh[np * 2][0] = q0; bh[np * 2][1] = q1;
                bh[np * 2 + 1][0] = q2; bh[np * 2 + 1][1] = q3;
            }
#pragma unroll
            for (int mt = 0; mt < 4; mt++)
#pragma unroll
                for (int nt = 0; nt < 4; nt++) MMA16816(acc[mt][nt], ahf[mt], bh[nt]);
            uint32_t bl[4][2];
#pragma unroll
            for (int np = 0; np < 2; np++) {
                uint32_t addr = bWl + (uint32_t)((wn + np * 16 + rB) * ASTRIDE + s * 16 + kB) * 2;
                uint32_t q0, q1, q2, q3;
                LDM_X4(q0, q1, q2, q3, addr);
                bl[np * 2][0] = q0; bl[np * 2][1] = q1;
                bl[np * 2 + 1][0] = q2; bl[np * 2 + 1][1] = q3;
            }
#pragma unroll
            for (int mt = 0; mt < 4; mt++)
#pragma unroll
                for (int nt = 0; nt < 4; nt++) MMA16816(acc[mt][nt], ahf[mt], bl[nt]);
            uint32_t alf[4][4];
#pragma unroll
            for (int mt = 0; mt < 4; mt++) {
                uint32_t addr = bAl + (uint32_t)((wm + mt * 16 + rA) * ASTRIDE + s * 16 + kA) * 2;
                LDM_X4(alf[mt][0], alf[mt][1], alf[mt][2], alf[mt][3], addr);
            }
#pragma unroll
            for (int mt = 0; mt < 4; mt++)
#pragma unroll
                for (int nt = 0; nt < 4; nt++) MMA16816(acc[mt][nt], alf[mt], bh[nt]);
        }
        __syncthreads();
    }

#pragma unroll
    for (int mt = 0; mt < 4; mt++) {
        int row0 = rbase + wm + mt * 16 + (lane >> 2);
        int row1 = row0 + 8;
#pragma unroll
        for (int nt = 0; nt < 4; nt++) {
            int col0 = cbase + wn + nt * 8 + (lane & 3) * 2;
            if (col0 < M) {
                float b0 = bias[col0];
                if (row0 < Nr) C[(size_t)row0 * M + col0] = acc[mt][nt][0] + b0;
                if (row1 < Nr) C[(size_t)row1 * M + col0] = acc[mt][nt][2] + b0;
            }
            if (col0 + 1 < M) {
                float b1 = bias[col0 + 1];
                if (row0 < Nr) C[(size_t)row0 * M + col0 + 1] = acc[mt][nt][1] + b1;
                if (row1 < Nr) C[(size_t)row1 * M + col0 + 1] = acc[mt][nt][3] + b1;
            }
        }
    }
}

// ---------------- GraphNorm ------------------------------------------------
#define GN_RB 64

__global__ void k_gn_stats(const float* __restrict__ h, const int* __restrict__ batch,
                           float* __restrict__ gsum, float* __restrict__ gsq) {
    int c = threadIdx.x;
    int r0 = blockIdx.x * GN_RB;
    int r1 = min(r0 + GN_RB, NN);
    int gcur = batch[r0];
    float s = 0.f, q = 0.f;
    for (int r = r0; r < r1; r++) {
        int g = batch[r];
        if (g != gcur) {
            atomicAdd(&gsum[gcur * HD + c], s);
            atomicAdd(&gsq[gcur * HD + c], q);
            s = 0.f; q = 0.f; gcur = g;
        }
        float v = h[(size_t)r * HD + c];
        s += v; q += v * v;
    }
    atomicAdd(&gsum[gcur * HD + c], s);
    atomicAdd(&gsq[gcur * HD + c], q);
}

// coef reads stats then zeroes them (ready for next layer / next replay)
__global__ void k_gn_coef(float* __restrict__ gsum, float* __restrict__ gsq,
                          const float* __restrict__ invsz,
                          const float* __restrict__ w, const float* __restrict__ b,
                          const float* __restrict__ a,
                          float* __restrict__ gS, float* __restrict__ gT) {
    int i = blockIdx.x * blockDim.x + threadIdx.x;
    if (i >= NG * HD) return;
    int g = i / HD, c = i - g * HD;
    float iv = invsz[g];
    float m = gsum[i] * iv;
    float e2 = gsq[i] * iv;
    gsum[i] = 0.f;
    gsq[i] = 0.f;
    float alc = a[c];
    float var = e2 - alc * (2.f - alc) * m * m;
    float S = rsqrtf(var + EPSV) * w[c];
    gS[i] = S;
    gT[i] = b[c] - alc * m * S;
}

__global__ void k_gn_apply2(const float* __restrict__ h, const int* __restrict__ batch,
                            const float* __restrict__ gS, const float* __restrict__ gT,
                            __nv_bfloat16* __restrict__ xh, __nv_bfloat16* __restrict__ xl) {
    int i4 = blockIdx.x * blockDim.x + threadIdx.x;
    const int n4 = NN * (HD / 4);
    if (i4 >= n4) return;
    int r = i4 >> 7;
    int c4 = (i4 & 127) * 4;
    int g = batch[r];
    float4 v = *((const float4*)h + i4);
    float4 S = *(const float4*)&gS[g * HD + c4];
    float4 T = *(const float4*)&gT[g * HD + c4];
    v.x = fmaxf(fmaf(v.x, S.x, T.x), 0.f);
    v.y = fmaxf(fmaf(v.y, S.y, T.y), 0.f);
    v.z = fmaxf(fmaf(v.z, S.z, T.z), 0.f);
    v.w = fmaxf(fmaf(v.w, S.w, T.w), 0.f);
    __nv_bfloat162 h01, h23, l01, l23;
    h01.x = __float2bfloat16_rn(v.x); h01.y = __float2bfloat16_rn(v.y);
    h23.x = __float2bfloat16_rn(v.z); h23.y = __float2bfloat16_rn(v.w);
    l01.x = __float2bfloat16_rn(v.x - __bfloat162float(h01.x));
    l01.y = __float2bfloat16_rn(v.y - __bfloat162float(h01.y));
    l23.x = __float2bfloat16_rn(v.z - __bfloat162float(h23.x));
    l23.y = __float2bfloat16_rn(v.w - __bfloat162float(h23.y));
    *(__nv_bfloat162*)(xh + (size_t)i4 * 4) = h01;
    *(__nv_bfloat162*)(xh + (size_t)i4 * 4 + 2) = h23;
    *(__nv_bfloat162*)(xl + (size_t)i4 * 4) = l01;
    *(__nv_bfloat162*)(xl + (size_t)i4 * 4 + 2) = l23;
}

// ---------------- host-side orchestration ----------------------------------
static float* symaddrf(const void* s) { void* p = nullptr; cudaGetSymbolAddress(&p, s); return (float*)p; }
static int* symaddri(const void* s) { void* p = nullptr; cudaGetSymbolAddress(&p, s); return (int*)p; }
static __nv_bfloat16* symaddrb(const void* s) { void* p = nullptr; cudaGetSymbolAddress(&p, s); return (__nv_bfloat16*)p; }

extern "C" void kernel_launch(void* const* d_in, const int* in_sizes, int n_in,
                              void* d_out, int out_size) {
    const float* x      = (const float*)d_in[0];
    const int*   ei     = (const int*)d_in[1];
    const int*   batch  = (const int*)d_in[2];
    const int*   src    = ei;
    const int*   dst    = ei + NE;

    const float* Wl[5] = {(const float*)d_in[3], (const float*)d_in[6], (const float*)d_in[9],
                          (const float*)d_in[12], (const float*)d_in[15]};
    const float* Wr[5] = {(const float*)d_in[4], (const float*)d_in[7], (const float*)d_in[10],
                          (const float*)d_in[13], (const float*)d_in[16]};
    const float* bb[5] = {(const float*)d_in[5], (const float*)d_in[8], (const float*)d_in[11],
                          (const float*)d_in[14], (const float*)d_in[17]};
    const float* gw[4] = {(const float*)d_in[18], (const float*)d_in[21], (const float*)d_in[24],
                          (const float*)d_in[27]};
    const float* gb_[4] = {(const float*)d_in[19], (const float*)d_in[22], (const float*)d_in[25],
                           (const float*)d_in[28]};
    const float* ga[4] = {(const float*)d_in[20], (const float*)d_in[23], (const float*)d_in[26],
                          (const float*)d_in[29]};

    float* h1     = symaddrf(g_h1);
    int*   degi   = symaddri(g_degi);
    int*   rowptr = symaddri(g_rowptr);
    int*   cursor = symaddri(g_cursor);
    int*   csr    = symaddri(g_csr);
    float* invsz  = symaddrf(g_invsz);
    float* gsum   = symaddrf(g_gsum);
    float* gsq    = symaddrf(g_gsq);
    float* gS     = symaddrf(g_gS);
    float* gT     = symaddrf(g_gT);
    __nv_bfloat16* ah = symaddrb(g_ah);
    __nv_bfloat16* al = symaddrb(g_al);
    __nv_bfloat16* xh = symaddrb(g_xh);
    __nv_bfloat16* xl = symaddrb(g_xl);
    __nv_bfloat16* wh = symaddrb(g_wh);
    __nv_bfloat16* wl = symaddrb(g_wl);

    cudaFuncSetAttribute(k_gemm_tc, cudaFuncAttributeMaxDynamicSharedMemorySize, GEMM_DYN);

    int wrows[5] = {HD, HD, HD, HD, OD};
    int wkin[5]  = {FD, HD, HD, HD, HD};
    int wkpad[5] = {FDP, HD, HD, HD, HD};
    WSegs segs;
    int off = 0;
    int offl[5], offr[5];
    for (int l = 0; l < 5; l++) {
        offl[l] = off;
        segs.s[2 * l] = {Wl[l], wrows[l], wkin[l], wkpad[l], off};
        off += wrows[l] * wkpad[l];
        offr[l] = off;
        segs.s[2 * l + 1] = {Wr[l], wrows[l], wkin[l], wkpad[l], off};
        off += wrows[l] * wkpad[l];
    }
    segs.total = off;   // == WTOT

    auto GEMM = [&](int l, const float* bias, float* C, int Mout, int K) {
        dim3 grid((Mout + GBN - 1) / GBN, (NN + GBM - 1) / GBM);
        k_gemm_tc<<<grid, 256, GEMM_DYN>>>(ah, al, wh + offl[l], wl + offl[l],
                                           xh, xl, wh + offr[l], wl + offr[l],
                                           bias, C, NN, Mout, K);
    };

    // ---- CSR build + group sizes + weight splits + stats zero (once) ----
    k_zero2i<<<(NN + 255) / 256, 256>>>(degi, cursor, NN);
    k_zero2f<<<(NG * HD + 255) / 256, 256>>>(gsum, gsq, NG * HD);
    k_count_i<<<(NE + 255) / 256, 256>>>(dst, degi, NE);
    k_scan2<<<1, 1024>>>(degi, rowptr);
    k_scatter<<<(NE + 255) / 256, 256>>>(src, dst, rowptr, cursor, csr);
    k_group_sizes<<<1, 32>>>(batch, invsz);
    k_split_all<<<(WTOT + 255) / 256, 256>>>(segs, wh, wl);

    auto gnorm = [&](float* h, const float* w, const float* bias, const float* alpha) {
        k_gn_stats<<<(NN + GN_RB - 1) / GN_RB, HD>>>(h, batch, gsum, gsq);
        k_gn_coef<<<(NG * HD + 255) / 256, 256>>>(gsum, gsq, invsz, w, bias, alpha, gS, gT);
        k_gn_apply2<<<(NN * (HD / 4) + 255) / 256, 256>>>(h, batch, gS, gT, xh, xl);
    };

    // ---- layer 1 (50 -> 512) ----
    k_aggcsr50<<<NN, 64>>>(x, rowptr, csr, ah, al);
    k_split<<<(NN * FDP + 255) / 256 > 65535 ? 65535 : (NN * FDP + 255) / 256, 256>>>(
        x, xh, xl, NN, FD, FDP);
    GEMM(0, bb[0], h1, HD, FDP);
    gnorm(h1, gw[0], gb_[0], ga[0]);

    // ---- layers 2..4 (512 -> 512) ----
    for (int l = 1; l <= 3; l++) {
        k_aggcsr512p<<<dim3(NN, 2), 64>>>(xh, xl, rowptr, csr, ah, al);
        GEMM(l, bb[l], h1, HD, HD);
        gnorm(h1, gw[l], gb_[l], ga[l]);
    }

    // ---- layer 5 (512 -> 121) -> d_out ----
    k_aggcsr512p<<<dim3(NN, 2), 64>>>(xh, xl, rowptr, csr, ah, al);
    GEMM(4, bb[4], (float*)d_out, OD, HD);
}